// round 14
// baseline (speedup 1.0000x reference)
#include <cuda_runtime.h>
#include <cuda_fp16.h>

#define NN 100000
#define EE 3200000
#define D 16
#define RS 32                 // accumulator row stride (floats) = 128B = one line
#define ATTN_SLOPE 0.2f
#define ACT_SLOPE 0.01f

// ---- scratch (device globals; no allocation allowed) ----
__device__ float  g_fs[NN * D];       // feat_src rows (fp32: feeds numer directly)
__device__ __half g_fdh[NN * D];      // feat_dst rows (fp16: only feeds the score)
__device__ float  g_acc[NN * RS];     // [numer[16], denom, pad...] one 128B line per node

static __device__ __forceinline__ float lrelu(float x, float s) {
    return x >= 0.0f ? x : s * x;
}

static __device__ __forceinline__ uint2 pack_half4(float4 v) {
    __half2 h01 = __floats2half2_rn(v.x, v.y);
    __half2 h23 = __floats2half2_rn(v.z, v.w);
    uint2 u;
    u.x = *reinterpret_cast<unsigned int*>(&h01);
    u.y = *reinterpret_cast<unsigned int*>(&h23);
    return u;
}
static __device__ __forceinline__ float4 unpack_half4(uint2 u) {
    float2 a = __half22float2(*reinterpret_cast<__half2*>(&u.x));
    float2 b = __half22float2(*reinterpret_cast<__half2*>(&u.y));
    return make_float4(a.x, a.y, b.x, b.y);
}

// L2-only gathers: no L1 line allocation/fill for ~100%-miss random access
static __device__ __forceinline__ float4 ldcg_f4(const float* p) {
    float4 v;
    asm volatile("ld.global.cg.v4.f32 {%0, %1, %2, %3}, [%4];"
                 : "=f"(v.x), "=f"(v.y), "=f"(v.z), "=f"(v.w) : "l"(p));
    return v;
}
static __device__ __forceinline__ uint2 ldcg_u2(const __half* p) {
    uint2 v;
    asm volatile("ld.global.cg.v2.b32 {%0, %1}, [%2];"
                 : "=r"(v.x), "=r"(v.y) : "l"(p));
    return v;
}
// streaming (evict-first) index loads
static __device__ __forceinline__ int2 ldcs_i2(const int* p) {
    int2 v;
    asm volatile("ld.global.cs.v2.b32 {%0, %1}, [%2];"
                 : "=r"(v.x), "=r"(v.y) : "l"(p));
    return v;
}

// ============================================================
// node kernels: 4 threads per node, each owns one float4 quarter
// ============================================================

__global__ void k_feat1(const float* __restrict__ h,
                        const float* __restrict__ Wsrc, const float* __restrict__ bsrc,
                        const float* __restrict__ Wdst, const float* __restrict__ bdst,
                        int n)
{
    __shared__ float4 sWs[D * 4], sWd[D * 4];   // [k][q]
    __shared__ float4 sbs[4], sbd[4];
    if (threadIdx.x < D * 4) {
        sWs[threadIdx.x] = reinterpret_cast<const float4*>(Wsrc)[threadIdx.x];
        sWd[threadIdx.x] = reinterpret_cast<const float4*>(Wdst)[threadIdx.x];
    }
    if (threadIdx.x < 4) {
        sbs[threadIdx.x] = reinterpret_cast<const float4*>(bsrc)[threadIdx.x];
        sbd[threadIdx.x] = reinterpret_cast<const float4*>(bdst)[threadIdx.x];
    }
    __syncthreads();
    int t  = blockIdx.x * blockDim.x + threadIdx.x;
    int nd = t >> 2;
    int q  = t & 3;
    if (nd >= n) return;

    const float4* hr = reinterpret_cast<const float4*>(h + (size_t)nd * D);
    float hv[D];
#pragma unroll
    for (int i = 0; i < 4; i++) {
        float4 v = hr[i];
        hv[4*i+0] = v.x; hv[4*i+1] = v.y; hv[4*i+2] = v.z; hv[4*i+3] = v.w;
    }
    float4 fs = sbs[q], fd = sbd[q];
#pragma unroll
    for (int k = 0; k < D; k++) {
        float hk = hv[k];
        float4 ws = sWs[k*4 + q];
        float4 wd = sWd[k*4 + q];
        fs.x = fmaf(hk, ws.x, fs.x); fs.y = fmaf(hk, ws.y, fs.y);
        fs.z = fmaf(hk, ws.z, fs.z); fs.w = fmaf(hk, ws.w, fs.w);
        fd.x = fmaf(hk, wd.x, fd.x); fd.y = fmaf(hk, wd.y, fd.y);
        fd.z = fmaf(hk, wd.z, fd.z); fd.w = fmaf(hk, wd.w, fd.w);
    }
    reinterpret_cast<float4*>(g_fs + (size_t)nd * D)[q] = fs;
    reinterpret_cast<uint2*>(g_fdh + (size_t)nd * D)[q] = pack_half4(fd);
    // zero only live bytes: numer quarter + (lane 0) denom
    float* pa = g_acc + (size_t)nd * RS;
    reinterpret_cast<float4*>(pa)[q] = make_float4(0.f, 0.f, 0.f, 0.f);
    if (q == 0) pa[16] = 0.0f;
}

__global__ void k_mid(const float* __restrict__ Wsrc, const float* __restrict__ bsrc,
                      const float* __restrict__ Wdst, const float* __restrict__ bdst,
                      int n)
{
    __shared__ float4 sWs[D * 4], sWd[D * 4];
    __shared__ float4 sbs[4], sbd[4];
    if (threadIdx.x < D * 4) {
        sWs[threadIdx.x] = reinterpret_cast<const float4*>(Wsrc)[threadIdx.x];
        sWd[threadIdx.x] = reinterpret_cast<const float4*>(Wdst)[threadIdx.x];
    }
    if (threadIdx.x < 4) {
        sbs[threadIdx.x] = reinterpret_cast<const float4*>(bsrc)[threadIdx.x];
        sbd[threadIdx.x] = reinterpret_cast<const float4*>(bdst)[threadIdx.x];
    }
    __syncthreads();
    int t  = blockIdx.x * blockDim.x + threadIdx.x;
    int nd = t >> 2;
    int q  = t & 3;
    if (nd >= n) return;

    float* row = g_acc + (size_t)nd * RS;
    float dn  = row[16];
    float inv = dn > 0.0f ? 1.0f / dn : 0.0f;
    const float4* np = reinterpret_cast<const float4*>(row);
    float hv[D];
#pragma unroll
    for (int i = 0; i < 4; i++) {
        float4 v = np[i];
        hv[4*i+0] = lrelu(v.x * inv, ACT_SLOPE);
        hv[4*i+1] = lrelu(v.y * inv, ACT_SLOPE);
        hv[4*i+2] = lrelu(v.z * inv, ACT_SLOPE);
        hv[4*i+3] = lrelu(v.w * inv, ACT_SLOPE);
    }
    float4 fs = sbs[q], fd = sbd[q];
#pragma unroll
    for (int k = 0; k < D; k++) {
        float hk = hv[k];
        float4 ws = sWs[k*4 + q];
        float4 wd = sWd[k*4 + q];
        fs.x = fmaf(hk, ws.x, fs.x); fs.y = fmaf(hk, ws.y, fs.y);
        fs.z = fmaf(hk, ws.z, fs.z); fs.w = fmaf(hk, ws.w, fs.w);
        fd.x = fmaf(hk, wd.x, fd.x); fd.y = fmaf(hk, wd.y, fd.y);
        fd.z = fmaf(hk, wd.z, fd.z); fd.w = fmaf(hk, wd.w, fd.w);
    }
    reinterpret_cast<float4*>(g_fs + (size_t)nd * D)[q] = fs;
    reinterpret_cast<uint2*>(g_fdh + (size_t)nd * D)[q] = pack_half4(fd);
    reinterpret_cast<float4*>(row)[q] = make_float4(0.f, 0.f, 0.f, 0.f);
    if (q == 0) row[16] = 0.0f;
}

// ============================================================
// fused edge pass (R8 structure): 4 lanes per edge, 2 edges per
// thread, int2 idx loads, gathers via .cg (no L1 fill).
// Softmax without max-shift (shift cancels exactly in numer/denom).
// ============================================================
__global__ void k_edge(const int* __restrict__ src, const int* __restrict__ dst,
                       const float* __restrict__ attn, int e)
{
    int t     = blockIdx.x * blockDim.x + threadIdx.x;
    int q     = t & 3;
    int group = t >> 2;
    int e0    = group * 2;
    if (e0 >= e) return;
    bool two  = (e0 + 1) < e;

    float4 a = __ldg(reinterpret_cast<const float4*>(attn) + q);

    int2 sv, dv;
    if (two) {
        sv = ldcs_i2(src + e0);
        dv = ldcs_i2(dst + e0);
    } else {
        sv.x = __ldg(src + e0); sv.y = sv.x;
        dv.x = __ldg(dst + e0); dv.y = dv.x;
    }

    // issue all four gathers up front (max MLP), L2-only
    float4 el0 = ldcg_f4(g_fs + (size_t)sv.x * D + q * 4);
    uint2  eu0 = ldcg_u2(g_fdh + (size_t)dv.x * D + q * 4);
    float4 el1 = ldcg_f4(g_fs + (size_t)sv.y * D + q * 4);
    uint2  eu1 = ldcg_u2(g_fdh + (size_t)dv.y * D + q * 4);
    float4 ed0 = unpack_half4(eu0);
    float4 ed1 = unpack_half4(eu1);

    float p0 = lrelu(el0.x + ed0.x, ATTN_SLOPE) * a.x
             + lrelu(el0.y + ed0.y, ATTN_SLOPE) * a.y
             + lrelu(el0.z + ed0.z, ATTN_SLOPE) * a.z
             + lrelu(el0.w + ed0.w, ATTN_SLOPE) * a.w;
    float p1 = lrelu(el1.x + ed1.x, ATTN_SLOPE) * a.x
             + lrelu(el1.y + ed1.y, ATTN_SLOPE) * a.y
             + lrelu(el1.z + ed1.z, ATTN_SLOPE) * a.z
             + lrelu(el1.w + ed1.w, ATTN_SLOPE) * a.w;

    p0 += __shfl_xor_sync(0xFFFFFFFFu, p0, 1);
    p0 += __shfl_xor_sync(0xFFFFFFFFu, p0, 2);
    p1 += __shfl_xor_sync(0xFFFFFFFFu, p1, 1);
    p1 += __shfl_xor_sync(0xFFFFFFFFu, p1, 2);

    float ex0 = __expf(p0);
    float ex1 = __expf(p1);

    if (q == 0) {
        atomicAdd(g_acc + (size_t)dv.x * RS + 16, ex0);
        if (two) atomicAdd(g_acc + (size_t)dv.y * RS + 16, ex1);
    }

    float* pn0 = g_acc + (size_t)dv.x * RS + q * 4;
    asm volatile("red.global.add.v4.f32 [%0], {%1, %2, %3, %4};"
                 :: "l"(pn0), "f"(ex0 * el0.x), "f"(ex0 * el0.y),
                    "f"(ex0 * el0.z), "f"(ex0 * el0.w) : "memory");
    if (two) {
        float* pn1 = g_acc + (size_t)dv.y * RS + q * 4;
        asm volatile("red.global.add.v4.f32 [%0], {%1, %2, %3, %4};"
                     :: "l"(pn1), "f"(ex1 * el1.x), "f"(ex1 * el1.y),
                        "f"(ex1 * el1.z), "f"(ex1 * el1.w) : "memory");
    }
}

// ---- layer-2 epilogue -> output ----
__global__ void k_fin(float* __restrict__ out, int n)
{
    int t  = blockIdx.x * blockDim.x + threadIdx.x;
    int nd = t >> 2;
    int q  = t & 3;
    if (nd >= n) return;
    const float* row = g_acc + (size_t)nd * RS;
    float dn  = row[16];
    float inv = dn > 0.0f ? 1.0f / dn : 0.0f;
    float4 v = reinterpret_cast<const float4*>(row)[q];
    reinterpret_cast<float4*>(out + (size_t)nd * D)[q] =
        make_float4(lrelu(v.x * inv, ACT_SLOPE),
                    lrelu(v.y * inv, ACT_SLOPE),
                    lrelu(v.z * inv, ACT_SLOPE),
                    lrelu(v.w * inv, ACT_SLOPE));
}

extern "C" void kernel_launch(void* const* d_in, const int* in_sizes, int n_in,
                              void* d_out, int out_size)
{
    const float* emb = (const float*)d_in[0];
    const int*   src1 = (const int*)d_in[1];
    const int*   dst1 = (const int*)d_in[2];
    const int*   src2 = (const int*)d_in[3];
    const int*   dst2 = (const int*)d_in[4];
    const float* Ws1 = (const float*)d_in[5];
    const float* bs1 = (const float*)d_in[6];
    const float* Wd1 = (const float*)d_in[7];
    const float* bd1 = (const float*)d_in[8];
    const float* at1 = (const float*)d_in[9];
    const float* Ws2 = (const float*)d_in[10];
    const float* bs2 = (const float*)d_in[11];
    const float* Wd2 = (const float*)d_in[12];
    const float* bd2 = (const float*)d_in[13];
    const float* at2 = (const float*)d_in[14];
    float* out = (float*)d_out;

    int n  = in_sizes[0] / D;
    int e1 = in_sizes[1];
    int e2 = in_sizes[3];

    dim3 tb(256);
    dim3 nb((unsigned)(((size_t)n * 4 + 255) / 256));
    // 4 lanes per edge, 2 edges per thread
    long long g1 = ((long long)(e1 + 1) / 2) * 4;
    long long g2 = ((long long)(e2 + 1) / 2) * 4;
    dim3 eb1((unsigned)((g1 + 255) / 256));
    dim3 eb2((unsigned)((g2 + 255) / 256));

    // layer 1
    k_feat1<<<nb, tb>>>(emb, Ws1, bs1, Wd1, bd1, n);
    k_edge <<<eb1, tb>>>(src1, dst1, at1, e1);
    // layer-1 epilogue + layer-2 feats
    k_mid  <<<nb, tb>>>(Ws2, bs2, Wd2, bd2, n);
    // layer 2
    k_edge <<<eb2, tb>>>(src2, dst2, at2, e2);
    k_fin  <<<nb, tb>>>(out, n);
}

// round 15
// speedup vs baseline: 1.0137x; 1.0137x over previous
#include <cuda_runtime.h>
#include <cuda_fp16.h>

#define NN 100000
#define EE 3200000
#define D 16
#define RS 32                 // accumulator row stride (floats) = 128B = one line
#define ATTN_SLOPE 0.2f
#define ACT_SLOPE 0.01f

// ---- scratch (device globals; no allocation allowed) ----
__device__ float  g_fs[NN * D];       // feat_src rows (fp32: feeds numer directly)
__device__ __half g_fdh[NN * D];      // feat_dst rows (fp16: only feeds the score)
__device__ float  g_acc[NN * RS];     // [numer[16], denom, pad...] one 128B line per node

static __device__ __forceinline__ float lrelu(float x, float s) {
    return x >= 0.0f ? x : s * x;
}

static __device__ __forceinline__ uint2 pack_half4(float4 v) {
    __half2 h01 = __floats2half2_rn(v.x, v.y);
    __half2 h23 = __floats2half2_rn(v.z, v.w);
    uint2 u;
    u.x = *reinterpret_cast<unsigned int*>(&h01);
    u.y = *reinterpret_cast<unsigned int*>(&h23);
    return u;
}
static __device__ __forceinline__ float4 unpack_half4(uint2 u) {
    float2 a = __half22float2(*reinterpret_cast<__half2*>(&u.x));
    float2 b = __half22float2(*reinterpret_cast<__half2*>(&u.y));
    return make_float4(a.x, a.y, b.x, b.y);
}

// ============================================================
// node kernels: 4 threads per node, each owns one float4 quarter
// ============================================================

__global__ void k_feat1(const float* __restrict__ h,
                        const float* __restrict__ Wsrc, const float* __restrict__ bsrc,
                        const float* __restrict__ Wdst, const float* __restrict__ bdst,
                        int n)
{
    __shared__ float4 sWs[D * 4], sWd[D * 4];   // [k][q]
    __shared__ float4 sbs[4], sbd[4];
    if (threadIdx.x < D * 4) {
        sWs[threadIdx.x] = reinterpret_cast<const float4*>(Wsrc)[threadIdx.x];
        sWd[threadIdx.x] = reinterpret_cast<const float4*>(Wdst)[threadIdx.x];
    }
    if (threadIdx.x < 4) {
        sbs[threadIdx.x] = reinterpret_cast<const float4*>(bsrc)[threadIdx.x];
        sbd[threadIdx.x] = reinterpret_cast<const float4*>(bdst)[threadIdx.x];
    }
    __syncthreads();
    int t  = blockIdx.x * blockDim.x + threadIdx.x;
    int nd = t >> 2;
    int q  = t & 3;
    if (nd >= n) return;

    const float4* hr = reinterpret_cast<const float4*>(h + (size_t)nd * D);
    float hv[D];
#pragma unroll
    for (int i = 0; i < 4; i++) {
        float4 v = hr[i];
        hv[4*i+0] = v.x; hv[4*i+1] = v.y; hv[4*i+2] = v.z; hv[4*i+3] = v.w;
    }
    float4 fs = sbs[q], fd = sbd[q];
#pragma unroll
    for (int k = 0; k < D; k++) {
        float hk = hv[k];
        float4 ws = sWs[k*4 + q];
        float4 wd = sWd[k*4 + q];
        fs.x = fmaf(hk, ws.x, fs.x); fs.y = fmaf(hk, ws.y, fs.y);
        fs.z = fmaf(hk, ws.z, fs.z); fs.w = fmaf(hk, ws.w, fs.w);
        fd.x = fmaf(hk, wd.x, fd.x); fd.y = fmaf(hk, wd.y, fd.y);
        fd.z = fmaf(hk, wd.z, fd.z); fd.w = fmaf(hk, wd.w, fd.w);
    }
    reinterpret_cast<float4*>(g_fs + (size_t)nd * D)[q] = fs;
    reinterpret_cast<uint2*>(g_fdh + (size_t)nd * D)[q] = pack_half4(fd);
    // zero only live bytes: numer quarter + (lane 0) denom
    float* pa = g_acc + (size_t)nd * RS;
    reinterpret_cast<float4*>(pa)[q] = make_float4(0.f, 0.f, 0.f, 0.f);
    if (q == 0) pa[16] = 0.0f;
}

__global__ void k_mid(const float* __restrict__ Wsrc, const float* __restrict__ bsrc,
                      const float* __restrict__ Wdst, const float* __restrict__ bdst,
                      int n)
{
    __shared__ float4 sWs[D * 4], sWd[D * 4];
    __shared__ float4 sbs[4], sbd[4];
    if (threadIdx.x < D * 4) {
        sWs[threadIdx.x] = reinterpret_cast<const float4*>(Wsrc)[threadIdx.x];
        sWd[threadIdx.x] = reinterpret_cast<const float4*>(Wdst)[threadIdx.x];
    }
    if (threadIdx.x < 4) {
        sbs[threadIdx.x] = reinterpret_cast<const float4*>(bsrc)[threadIdx.x];
        sbd[threadIdx.x] = reinterpret_cast<const float4*>(bdst)[threadIdx.x];
    }
    __syncthreads();
    int t  = blockIdx.x * blockDim.x + threadIdx.x;
    int nd = t >> 2;
    int q  = t & 3;
    if (nd >= n) return;

    float* row = g_acc + (size_t)nd * RS;
    float dn  = row[16];
    float inv = dn > 0.0f ? 1.0f / dn : 0.0f;
    const float4* np = reinterpret_cast<const float4*>(row);
    float hv[D];
#pragma unroll
    for (int i = 0; i < 4; i++) {
        float4 v = np[i];
        hv[4*i+0] = lrelu(v.x * inv, ACT_SLOPE);
        hv[4*i+1] = lrelu(v.y * inv, ACT_SLOPE);
        hv[4*i+2] = lrelu(v.z * inv, ACT_SLOPE);
        hv[4*i+3] = lrelu(v.w * inv, ACT_SLOPE);
    }
    float4 fs = sbs[q], fd = sbd[q];
#pragma unroll
    for (int k = 0; k < D; k++) {
        float hk = hv[k];
        float4 ws = sWs[k*4 + q];
        float4 wd = sWd[k*4 + q];
        fs.x = fmaf(hk, ws.x, fs.x); fs.y = fmaf(hk, ws.y, fs.y);
        fs.z = fmaf(hk, ws.z, fs.z); fs.w = fmaf(hk, ws.w, fs.w);
        fd.x = fmaf(hk, wd.x, fd.x); fd.y = fmaf(hk, wd.y, fd.y);
        fd.z = fmaf(hk, wd.z, fd.z); fd.w = fmaf(hk, wd.w, fd.w);
    }
    reinterpret_cast<float4*>(g_fs + (size_t)nd * D)[q] = fs;
    reinterpret_cast<uint2*>(g_fdh + (size_t)nd * D)[q] = pack_half4(fd);
    reinterpret_cast<float4*>(row)[q] = make_float4(0.f, 0.f, 0.f, 0.f);
    if (q == 0) row[16] = 0.0f;
}

// ============================================================
// fused edge pass (R8 structure, best measured): 4 lanes per edge,
// 2 edges per thread, int2 idx loads, plain cached gathers.
// Denom atomics spread across lanes 0/1 (one predicated instruction).
// Softmax without max-shift (shift cancels exactly in numer/denom).
// ============================================================
__global__ void __launch_bounds__(256)
k_edge(const int* __restrict__ src, const int* __restrict__ dst,
       const float* __restrict__ attn, int e)
{
    int t     = blockIdx.x * blockDim.x + threadIdx.x;
    int q     = t & 3;
    int group = t >> 2;
    int e0    = group * 2;
    if (e0 >= e) return;
    bool two  = (e0 + 1) < e;

    float4 a = __ldg(reinterpret_cast<const float4*>(attn) + q);

    int2 sv, dv;
    if (two) {
        sv = __ldg(reinterpret_cast<const int2*>(src + e0));
        dv = __ldg(reinterpret_cast<const int2*>(dst + e0));
    } else {
        sv.x = __ldg(src + e0); sv.y = sv.x;
        dv.x = __ldg(dst + e0); dv.y = dv.x;
    }

    // issue all four gathers up front (max MLP)
    float4 el0 = *(reinterpret_cast<const float4*>(g_fs + (size_t)sv.x * D) + q);
    uint2  eu0 = *(reinterpret_cast<const uint2*>(g_fdh + (size_t)dv.x * D) + q);
    float4 el1 = *(reinterpret_cast<const float4*>(g_fs + (size_t)sv.y * D) + q);
    uint2  eu1 = *(reinterpret_cast<const uint2*>(g_fdh + (size_t)dv.y * D) + q);
    float4 ed0 = unpack_half4(eu0);
    float4 ed1 = unpack_half4(eu1);

    float p0 = lrelu(el0.x + ed0.x, ATTN_SLOPE) * a.x
             + lrelu(el0.y + ed0.y, ATTN_SLOPE) * a.y
             + lrelu(el0.z + ed0.z, ATTN_SLOPE) * a.z
             + lrelu(el0.w + ed0.w, ATTN_SLOPE) * a.w;
    float p1 = lrelu(el1.x + ed1.x, ATTN_SLOPE) * a.x
             + lrelu(el1.y + ed1.y, ATTN_SLOPE) * a.y
             + lrelu(el1.z + ed1.z, ATTN_SLOPE) * a.z
             + lrelu(el1.w + ed1.w, ATTN_SLOPE) * a.w;

    p0 += __shfl_xor_sync(0xFFFFFFFFu, p0, 1);
    p0 += __shfl_xor_sync(0xFFFFFFFFu, p0, 2);
    p1 += __shfl_xor_sync(0xFFFFFFFFu, p1, 1);
    p1 += __shfl_xor_sync(0xFFFFFFFFu, p1, 2);

    float ex0 = __expf(p0);
    float ex1 = __expf(p1);

    // denom: lane 0 carries edge 0, lane 1 carries edge 1 -> one
    // predicated atomic instruction, no serial chain on lane 0.
    {
        int   dq = (q == 0) ? dv.x : dv.y;
        float xq = (q == 0) ? ex0  : ex1;
        bool  on = (q == 0) | ((q == 1) & two);
        if (on) atomicAdd(g_acc + (size_t)dq * RS + 16, xq);
    }

    float* pn0 = g_acc + (size_t)dv.x * RS + q * 4;
    asm volatile("red.global.add.v4.f32 [%0], {%1, %2, %3, %4};"
                 :: "l"(pn0), "f"(ex0 * el0.x), "f"(ex0 * el0.y),
                    "f"(ex0 * el0.z), "f"(ex0 * el0.w) : "memory");
    if (two) {
        float* pn1 = g_acc + (size_t)dv.y * RS + q * 4;
        asm volatile("red.global.add.v4.f32 [%0], {%1, %2, %3, %4};"
                     :: "l"(pn1), "f"(ex1 * el1.x), "f"(ex1 * el1.y),
                        "f"(ex1 * el1.z), "f"(ex1 * el1.w) : "memory");
    }
}

// ---- layer-2 epilogue -> output ----
__global__ void k_fin(float* __restrict__ out, int n)
{
    int t  = blockIdx.x * blockDim.x + threadIdx.x;
    int nd = t >> 2;
    int q  = t & 3;
    if (nd >= n) return;
    const float* row = g_acc + (size_t)nd * RS;
    float dn  = row[16];
    float inv = dn > 0.0f ? 1.0f / dn : 0.0f;
    float4 v = reinterpret_cast<const float4*>(row)[q];
    reinterpret_cast<float4*>(out + (size_t)nd * D)[q] =
        make_float4(lrelu(v.x * inv, ACT_SLOPE),
                    lrelu(v.y * inv, ACT_SLOPE),
                    lrelu(v.z * inv, ACT_SLOPE),
                    lrelu(v.w * inv, ACT_SLOPE));
}

extern "C" void kernel_launch(void* const* d_in, const int* in_sizes, int n_in,
                              void* d_out, int out_size)
{
    const float* emb = (const float*)d_in[0];
    const int*   src1 = (const int*)d_in[1];
    const int*   dst1 = (const int*)d_in[2];
    const int*   src2 = (const int*)d_in[3];
    const int*   dst2 = (const int*)d_in[4];
    const float* Ws1 = (const float*)d_in[5];
    const float* bs1 = (const float*)d_in[6];
    const float* Wd1 = (const float*)d_in[7];
    const float* bd1 = (const float*)d_in[8];
    const float* at1 = (const float*)d_in[9];
    const float* Ws2 = (const float*)d_in[10];
    const float* bs2 = (const float*)d_in[11];
    const float* Wd2 = (const float*)d_in[12];
    const float* bd2 = (const float*)d_in[13];
    const float* at2 = (const float*)d_in[14];
    float* out = (float*)d_out;

    int n  = in_sizes[0] / D;
    int e1 = in_sizes[1];
    int e2 = in_sizes[3];

    dim3 tb(256);
    dim3 nb((unsigned)(((size_t)n * 4 + 255) / 256));
    // 4 lanes per edge, 2 edges per thread
    long long g1 = ((long long)(e1 + 1) / 2) * 4;
    long long g2 = ((long long)(e2 + 1) / 2) * 4;
    dim3 eb1((unsigned)((g1 + 255) / 256));
    dim3 eb2((unsigned)((g2 + 255) / 256));

    // layer 1
    k_feat1<<<nb, tb>>>(emb, Ws1, bs1, Wd1, bd1, n);
    k_edge <<<eb1, tb>>>(src1, dst1, at1, e1);
    // layer-1 epilogue + layer-2 feats
    k_mid  <<<nb, tb>>>(Ws2, bs2, Wd2, bd2, n);
    // layer 2
    k_edge <<<eb2, tb>>>(src2, dst2, at2, e2);
    k_fin  <<<nb, tb>>>(out, n);
}

// round 16
// speedup vs baseline: 1.0661x; 1.0517x over previous
#include <cuda_runtime.h>
#include <cuda_fp16.h>

#define NN 100000
#define EE 3200000
#define D 16
#define ATTN_SLOPE 0.2f
#define ACT_SLOPE 0.01f

// ---- scratch (device globals; no allocation allowed) ----
__device__ float  g_fs[NN * D];     // feat_src rows (fp32: feeds numer directly)
__device__ __half g_fdh[NN * D];    // feat_dst rows (fp16: only feeds the score)
__device__ float  g_numer[NN * D];  // sum(ex * el) per dst
__device__ float  g_denom[NN];      // sum(ex) per dst

static __device__ __forceinline__ float lrelu(float x, float s) {
    return x >= 0.0f ? x : s * x;
}

static __device__ __forceinline__ uint2 pack_half4(float4 v) {
    __half2 h01 = __floats2half2_rn(v.x, v.y);
    __half2 h23 = __floats2half2_rn(v.z, v.w);
    uint2 u;
    u.x = *reinterpret_cast<unsigned int*>(&h01);
    u.y = *reinterpret_cast<unsigned int*>(&h23);
    return u;
}
static __device__ __forceinline__ float4 unpack_half4(uint2 u) {
    float2 a = __half22float2(*reinterpret_cast<__half2*>(&u.x));
    float2 b = __half22float2(*reinterpret_cast<__half2*>(&u.y));
    return make_float4(a.x, a.y, b.x, b.y);
}

// ============================================================
// node kernels: 4 threads per node, each owns one float4 quarter
// ============================================================

// ---- layer 1 prologue: feats + accumulator init ----
__global__ void k_feat1(const float* __restrict__ h,
                        const float* __restrict__ Wsrc, const float* __restrict__ bsrc,
                        const float* __restrict__ Wdst, const float* __restrict__ bdst,
                        int n)
{
    __shared__ float4 sWs[D * 4], sWd[D * 4];   // [k][q]
    __shared__ float4 sbs[4], sbd[4];
    if (threadIdx.x < D * 4) {
        sWs[threadIdx.x] = reinterpret_cast<const float4*>(Wsrc)[threadIdx.x];
        sWd[threadIdx.x] = reinterpret_cast<const float4*>(Wdst)[threadIdx.x];
    }
    if (threadIdx.x < 4) {
        sbs[threadIdx.x] = reinterpret_cast<const float4*>(bsrc)[threadIdx.x];
        sbd[threadIdx.x] = reinterpret_cast<const float4*>(bdst)[threadIdx.x];
    }
    __syncthreads();
    int t  = blockIdx.x * blockDim.x + threadIdx.x;
    int nd = t >> 2;
    int q  = t & 3;
    if (nd >= n) return;

    const float4* hr = reinterpret_cast<const float4*>(h + (size_t)nd * D);
    float hv[D];
#pragma unroll
    for (int i = 0; i < 4; i++) {
        float4 v = hr[i];
        hv[4*i+0] = v.x; hv[4*i+1] = v.y; hv[4*i+2] = v.z; hv[4*i+3] = v.w;
    }
    float4 fs = sbs[q], fd = sbd[q];
#pragma unroll
    for (int k = 0; k < D; k++) {
        float hk = hv[k];
        float4 ws = sWs[k*4 + q];
        float4 wd = sWd[k*4 + q];
        fs.x = fmaf(hk, ws.x, fs.x); fs.y = fmaf(hk, ws.y, fs.y);
        fs.z = fmaf(hk, ws.z, fs.z); fs.w = fmaf(hk, ws.w, fs.w);
        fd.x = fmaf(hk, wd.x, fd.x); fd.y = fmaf(hk, wd.y, fd.y);
        fd.z = fmaf(hk, wd.z, fd.z); fd.w = fmaf(hk, wd.w, fd.w);
    }
    reinterpret_cast<float4*>(g_fs + (size_t)nd * D)[q] = fs;
    reinterpret_cast<uint2*>(g_fdh + (size_t)nd * D)[q] = pack_half4(fd);
    reinterpret_cast<float4*>(g_numer + (size_t)nd * D)[q] = make_float4(0.f, 0.f, 0.f, 0.f);
    if (q == 0) g_denom[nd] = 0.0f;
}

// ---- layer-1 epilogue fused with layer-2 feats ----
__global__ void k_mid(const float* __restrict__ Wsrc, const float* __restrict__ bsrc,
                      const float* __restrict__ Wdst, const float* __restrict__ bdst,
                      int n)
{
    __shared__ float4 sWs[D * 4], sWd[D * 4];
    __shared__ float4 sbs[4], sbd[4];
    if (threadIdx.x < D * 4) {
        sWs[threadIdx.x] = reinterpret_cast<const float4*>(Wsrc)[threadIdx.x];
        sWd[threadIdx.x] = reinterpret_cast<const float4*>(Wdst)[threadIdx.x];
    }
    if (threadIdx.x < 4) {
        sbs[threadIdx.x] = reinterpret_cast<const float4*>(bsrc)[threadIdx.x];
        sbd[threadIdx.x] = reinterpret_cast<const float4*>(bdst)[threadIdx.x];
    }
    __syncthreads();
    int t  = blockIdx.x * blockDim.x + threadIdx.x;
    int nd = t >> 2;
    int q  = t & 3;
    if (nd >= n) return;

    float dn  = g_denom[nd];
    float inv = dn > 0.0f ? 1.0f / dn : 0.0f;
    const float4* np = reinterpret_cast<const float4*>(g_numer + (size_t)nd * D);
    float hv[D];
#pragma unroll
    for (int i = 0; i < 4; i++) {
        float4 v = np[i];
        hv[4*i+0] = lrelu(v.x * inv, ACT_SLOPE);
        hv[4*i+1] = lrelu(v.y * inv, ACT_SLOPE);
        hv[4*i+2] = lrelu(v.z * inv, ACT_SLOPE);
        hv[4*i+3] = lrelu(v.w * inv, ACT_SLOPE);
    }
    float4 fs = sbs[q], fd = sbd[q];
#pragma unroll
    for (int k = 0; k < D; k++) {
        float hk = hv[k];
        float4 ws = sWs[k*4 + q];
        float4 wd = sWd[k*4 + q];
        fs.x = fmaf(hk, ws.x, fs.x); fs.y = fmaf(hk, ws.y, fs.y);
        fs.z = fmaf(hk, ws.z, fs.z); fs.w = fmaf(hk, ws.w, fs.w);
        fd.x = fmaf(hk, wd.x, fd.x); fd.y = fmaf(hk, wd.y, fd.y);
        fd.z = fmaf(hk, wd.z, fd.z); fd.w = fmaf(hk, wd.w, fd.w);
    }
    reinterpret_cast<float4*>(g_fs + (size_t)nd * D)[q] = fs;
    reinterpret_cast<uint2*>(g_fdh + (size_t)nd * D)[q] = pack_half4(fd);
    reinterpret_cast<float4*>(g_numer + (size_t)nd * D)[q] = make_float4(0.f, 0.f, 0.f, 0.f);
    if (q == 0) g_denom[nd] = 0.0f;
}

// ============================================================
// fused edge pass: 4 lanes per edge, 2 edges per thread.
// fd gathered as fp16 (half the sectors); softmax without max-shift
// (shift cancels exactly in numer/denom; exp(score) bounded here).
// ============================================================
__global__ void k_edge(const int* __restrict__ src, const int* __restrict__ dst,
                       const float* __restrict__ attn, int e)
{
    int t     = blockIdx.x * blockDim.x + threadIdx.x;
    int q     = t & 3;
    int group = t >> 2;
    int e0    = group * 2;
    if (e0 >= e) return;
    bool two  = (e0 + 1) < e;

    float4 a = __ldg(reinterpret_cast<const float4*>(attn) + q);

    int2 sv, dv;
    if (two) {
        sv = __ldg(reinterpret_cast<const int2*>(src + e0));
        dv = __ldg(reinterpret_cast<const int2*>(dst + e0));
    } else {
        sv.x = __ldg(src + e0); sv.y = sv.x;
        dv.x = __ldg(dst + e0); dv.y = dv.x;
    }

    // issue all four gathers up front (max MLP)
    float4 el0 = *(reinterpret_cast<const float4*>(g_fs + (size_t)sv.x * D) + q);
    uint2  eu0 = *(reinterpret_cast<const uint2*>(g_fdh + (size_t)dv.x * D) + q);
    float4 el1 = *(reinterpret_cast<const float4*>(g_fs + (size_t)sv.y * D) + q);
    uint2  eu1 = *(reinterpret_cast<const uint2*>(g_fdh + (size_t)dv.y * D) + q);
    float4 ed0 = unpack_half4(eu0);
    float4 ed1 = unpack_half4(eu1);

    float p0 = lrelu(el0.x + ed0.x, ATTN_SLOPE) * a.x
             + lrelu(el0.y + ed0.y, ATTN_SLOPE) * a.y
             + lrelu(el0.z + ed0.z, ATTN_SLOPE) * a.z
             + lrelu(el0.w + ed0.w, ATTN_SLOPE) * a.w;
    float p1 = lrelu(el1.x + ed1.x, ATTN_SLOPE) * a.x
             + lrelu(el1.y + ed1.y, ATTN_SLOPE) * a.y
             + lrelu(el1.z + ed1.z, ATTN_SLOPE) * a.z
             + lrelu(el1.w + ed1.w, ATTN_SLOPE) * a.w;

    p0 += __shfl_xor_sync(0xFFFFFFFFu, p0, 1);
    p0 += __shfl_xor_sync(0xFFFFFFFFu, p0, 2);
    p1 += __shfl_xor_sync(0xFFFFFFFFu, p1, 1);
    p1 += __shfl_xor_sync(0xFFFFFFFFu, p1, 2);

    float ex0 = __expf(p0);
    float ex1 = __expf(p1);

    if (q == 0) {
        atomicAdd(&g_denom[dv.x], ex0);
        if (two) atomicAdd(&g_denom[dv.y], ex1);
    }

    float* pn0 = g_numer + (size_t)dv.x * D + q * 4;
    asm volatile("red.global.add.v4.f32 [%0], {%1, %2, %3, %4};"
                 :: "l"(pn0), "f"(ex0 * el0.x), "f"(ex0 * el0.y),
                    "f"(ex0 * el0.z), "f"(ex0 * el0.w) : "memory");
    if (two) {
        float* pn1 = g_numer + (size_t)dv.y * D + q * 4;
        asm volatile("red.global.add.v4.f32 [%0], {%1, %2, %3, %4};"
                     :: "l"(pn1), "f"(ex1 * el1.x), "f"(ex1 * el1.y),
                        "f"(ex1 * el1.z), "f"(ex1 * el1.w) : "memory");
    }
}

// ---- layer-2 epilogue -> output ----
__global__ void k_fin(float* __restrict__ out, int n)
{
    int t  = blockIdx.x * blockDim.x + threadIdx.x;
    int nd = t >> 2;
    int q  = t & 3;
    if (nd >= n) return;
    float dn  = g_denom[nd];
    float inv = dn > 0.0f ? 1.0f / dn : 0.0f;
    float4 v = reinterpret_cast<const float4*>(g_numer + (size_t)nd * D)[q];
    reinterpret_cast<float4*>(out + (size_t)nd * D)[q] =
        make_float4(lrelu(v.x * inv, ACT_SLOPE),
                    lrelu(v.y * inv, ACT_SLOPE),
                    lrelu(v.z * inv, ACT_SLOPE),
                    lrelu(v.w * inv, ACT_SLOPE));
}

extern "C" void kernel_launch(void* const* d_in, const int* in_sizes, int n_in,
                              void* d_out, int out_size)
{
    const float* emb = (const float*)d_in[0];
    const int*   src1 = (const int*)d_in[1];
    const int*   dst1 = (const int*)d_in[2];
    const int*   src2 = (const int*)d_in[3];
    const int*   dst2 = (const int*)d_in[4];
    const float* Ws1 = (const float*)d_in[5];
    const float* bs1 = (const float*)d_in[6];
    const float* Wd1 = (const float*)d_in[7];
    const float* bd1 = (const float*)d_in[8];
    const float* at1 = (const float*)d_in[9];
    const float* Ws2 = (const float*)d_in[10];
    const float* bs2 = (const float*)d_in[11];
    const float* Wd2 = (const float*)d_in[12];
    const float* bd2 = (const float*)d_in[13];
    const float* at2 = (const float*)d_in[14];
    float* out = (float*)d_out;

    int n  = in_sizes[0] / D;
    int e1 = in_sizes[1];
    int e2 = in_sizes[3];

    dim3 tb(256);
    dim3 nb((unsigned)(((size_t)n * 4 + 255) / 256));
    // 4 lanes per edge, 2 edges per thread
    long long g1 = ((long long)(e1 + 1) / 2) * 4;
    long long g2 = ((long long)(e2 + 1) / 2) * 4;
    dim3 eb1((unsigned)((g1 + 255) / 256));
    dim3 eb2((unsigned)((g2 + 255) / 256));

    // layer 1
    k_feat1<<<nb, tb>>>(emb, Ws1, bs1, Wd1, bd1, n);
    k_edge <<<eb1, tb>>>(src1, dst1, at1, e1);
    // layer-1 epilogue + layer-2 feats
    k_mid  <<<nb, tb>>>(Ws2, bs2, Wd2, bd2, n);
    // layer 2
    k_edge <<<eb2, tb>>>(src2, dst2, at2, e2);
    k_fin  <<<nb, tb>>>(out, n);
}